// round 1
// baseline (speedup 1.0000x reference)
#include <cuda_runtime.h>

typedef unsigned long long u64;

#define NSTEP 256   // C2
#define NPAIR 512   // H2
#define RPB   8     // batch rows per block
#define G     4     // f32x2 groups (2 rows each)

// Precomputed rotation coefficients (6.29 MB total, fits L2)
__device__ float4 g_cA4[NSTEP * NPAIR];   // (dr, di, or, oi) for rotation A, pair j, step c
__device__ float2 g_cA2[NSTEP * NPAIR];   // (ct, st) for rotation A
__device__ float4 g_cB4[NSTEP * NPAIR];   // (dr, di, or, oi) for rotation B (v-role of thread t)
__device__ float2 g_cB2s[NSTEP * NPAIR];  // (ct, st) of pair (t-1 mod 512)  [pre-shifted]

__device__ __forceinline__ u64 pk2(float x) {
    u64 r; asm("mov.b64 %0, {%1, %1};" : "=l"(r) : "f"(x)); return r;
}
__device__ __forceinline__ u64 pk(float lo, float hi) {
    u64 r; asm("mov.b64 %0, {%1, %2};" : "=l"(r) : "f"(lo), "f"(hi)); return r;
}
__device__ __forceinline__ void upk(u64 v, float& lo, float& hi) {
    asm("mov.b64 {%0, %1}, %2;" : "=f"(lo), "=f"(hi) : "l"(v));
}
__device__ __forceinline__ u64 mul2(u64 a, u64 b) {
    u64 r; asm("mul.rn.f32x2 %0, %1, %2;" : "=l"(r) : "l"(a), "l"(b)); return r;
}
__device__ __forceinline__ u64 fma2(u64 a, u64 b, u64 c) {
    u64 r; asm("fma.rn.f32x2 %0, %1, %2, %3;" : "=l"(r) : "l"(a), "l"(b), "l"(c)); return r;
}

// phi/theta arrays: (H2=512, C2=256) row-major -> [j*256 + c]
__global__ void coeff_kernel(const float* __restrict__ phi0, const float* __restrict__ th0,
                             const float* __restrict__ phi1, const float* __restrict__ th1) {
    int idx = blockIdx.x * blockDim.x + threadIdx.x;
    if (idx >= NSTEP * NPAIR) return;
    int j = idx & (NPAIR - 1);
    int c = idx >> 9;

    float sp, cp, st, ct;
    sincosf(phi0[j * NSTEP + c], &sp, &cp);
    sincosf(th0[j * NSTEP + c], &st, &ct);
    g_cA4[c * NPAIR + j] = make_float4(cp * ct, sp * ct, -cp * st, -sp * st);
    g_cA2[c * NPAIR + j] = make_float2(ct, st);

    sincosf(phi1[j * NSTEP + c], &sp, &cp);
    sincosf(th1[j * NSTEP + c], &st, &ct);
    g_cB4[c * NPAIR + j] = make_float4(cp * ct, sp * ct, -cp * st, -sp * st);
    // pair j's (ct, st) is consumed by thread j+1 (its u = element 2(j+1) is the
    // second element of rotation-B pair j); wraparound: pair 511 -> thread 0.
    g_cB2s[c * NPAIR + ((j + 1) & (NPAIR - 1))] = make_float2(ct, st);
}

// Thread t owns complex pair (x[2t], x[2t+1]) = (u, v) for 8 batch rows,
// packed 2 rows per f32x2 register. Whole H dimension lives in one block.
__global__ void __launch_bounds__(512, 1)
eunn_kernel(const float4* __restrict__ xin, float4* __restrict__ xout) {
    const int t    = threadIdx.x;
    const int lane = t & 31;
    const int w    = t >> 5;
    const int row0 = blockIdx.x * RPB;
    const u64 SGN  = 0x8000000080000000ULL;

    u64 ur[G], ui[G], vr[G], vi[G];
#pragma unroll
    for (int g = 0; g < G; g++) {
        float4 a = xin[(size_t)(row0 + 2 * g) * NPAIR + t];
        float4 b = xin[(size_t)(row0 + 2 * g + 1) * NPAIR + t];
        ur[g] = pk(a.x, b.x); ui[g] = pk(a.y, b.y);
        vr[g] = pk(a.z, b.z); vi[g] = pk(a.w, b.w);
    }

    // Double-buffered warp-boundary exchange (one __syncthreads per step)
    __shared__ u64 sUr[2][G][16], sUi[2][G][16], sVr[2][G][16], sVi[2][G][16];

    float4 a4 = g_cA4[t]; float2 a2 = g_cA2[t];
    float4 b4 = g_cB4[t]; float2 b2 = g_cB2s[t];

    for (int c = 0; c < NSTEP; c++) {
        // Prefetch next step's coefficients (hides L2 latency under FMA work)
        float4 na4 = a4, nb4 = b4; float2 na2 = a2, nb2 = b2;
        if (c + 1 < NSTEP) {
            int o = (c + 1) * NPAIR + t;
            na4 = g_cA4[o]; na2 = g_cA2[o]; nb4 = g_cB4[o]; nb2 = g_cB2s[o];
        }

        // ---- Rotation A: pairs (2t, 2t+1), purely local ----
        {
            u64 drA = pk2(a4.x), diA = pk2(a4.y), orA = pk2(a4.z), oiA = pk2(a4.w);
            u64 ctA = pk2(a2.x), stA = pk2(a2.y);
            u64 ndiA = diA ^ SGN, noiA = oiA ^ SGN;
#pragma unroll
            for (int g = 0; g < G; g++) {
                u64 t0 = mul2(drA, ur[g]); t0 = fma2(ndiA, ui[g], t0);
                t0 = fma2(orA, vr[g], t0); t0 = fma2(noiA, vi[g], t0);
                u64 t1 = mul2(drA, ui[g]); t1 = fma2(diA, ur[g], t1);
                t1 = fma2(orA, vi[g], t1); t1 = fma2(oiA, vr[g], t1);
                u64 t2 = mul2(ctA, vr[g]); t2 = fma2(stA, ur[g], t2);
                u64 t3 = mul2(ctA, vi[g]); t3 = fma2(stA, ui[g], t3);
                ur[g] = t0; ui[g] = t1; vr[g] = t2; vi[g] = t3;
            }
        }

        const int buf = c & 1;
        if (lane == 0) {
#pragma unroll
            for (int g = 0; g < G; g++) { sUr[buf][g][w] = ur[g]; sUi[buf][g][w] = ui[g]; }
        }
        if (lane == 31) {
#pragma unroll
            for (int g = 0; g < G; g++) { sVr[buf][g][w] = vr[g]; sVi[buf][g][w] = vi[g]; }
        }
        __syncthreads();

        // ---- Rotation B: pairs (2t+1, 2t+2 mod 1024) ----
        // v_t' = dB*v_t + oB*u_{t+1};  u_t' = ctB[t-1]*u_t + stB[t-1]*v_{t-1}
        {
            u64 drB = pk2(b4.x), diB = pk2(b4.y), orB = pk2(b4.z), oiB = pk2(b4.w);
            u64 ctm = pk2(b2.x), stm = pk2(b2.y);
            u64 ndiB = diB ^ SGN, noiB = oiB ^ SGN;
            const int wn = (w + 1) & 15, wp = (w + 15) & 15;
#pragma unroll
            for (int g = 0; g < G; g++) {
                u64 unr = __shfl_down_sync(0xffffffffu, ur[g], 1);
                u64 uni = __shfl_down_sync(0xffffffffu, ui[g], 1);
                u64 vpr = __shfl_up_sync(0xffffffffu, vr[g], 1);
                u64 vpi = __shfl_up_sync(0xffffffffu, vi[g], 1);
                if (lane == 31) { unr = sUr[buf][g][wn]; uni = sUi[buf][g][wn]; }
                if (lane == 0)  { vpr = sVr[buf][g][wp]; vpi = sVi[buf][g][wp]; }

                u64 t0 = mul2(drB, vr[g]); t0 = fma2(ndiB, vi[g], t0);
                t0 = fma2(orB, unr, t0);   t0 = fma2(noiB, uni, t0);
                u64 t1 = mul2(drB, vi[g]); t1 = fma2(diB, vr[g], t1);
                t1 = fma2(orB, uni, t1);   t1 = fma2(oiB, unr, t1);
                u64 t2 = mul2(ctm, ur[g]); t2 = fma2(stm, vpr, t2);
                u64 t3 = mul2(ctm, ui[g]); t3 = fma2(stm, vpi, t3);
                vr[g] = t0; vi[g] = t1; ur[g] = t2; ui[g] = t3;
            }
        }

        a4 = na4; a2 = na2; b4 = nb4; b2 = nb2;
    }

#pragma unroll
    for (int g = 0; g < G; g++) {
        float x0, x1, y0, y1, z0, z1, q0, q1;
        upk(ur[g], x0, x1); upk(ui[g], y0, y1);
        upk(vr[g], z0, z1); upk(vi[g], q0, q1);
        xout[(size_t)(row0 + 2 * g) * NPAIR + t]     = make_float4(x0, y0, z0, q0);
        xout[(size_t)(row0 + 2 * g + 1) * NPAIR + t] = make_float4(x1, y1, z1, q1);
    }
}

extern "C" void kernel_launch(void* const* d_in, const int* in_sizes, int n_in,
                              void* d_out, int out_size) {
    const float* x    = (const float*)d_in[0];
    const float* phi0 = (const float*)d_in[1];
    const float* th0  = (const float*)d_in[2];
    const float* phi1 = (const float*)d_in[3];
    const float* th1  = (const float*)d_in[4];

    coeff_kernel<<<(NSTEP * NPAIR + 255) / 256, 256>>>(phi0, th0, phi1, th1);
    eunn_kernel<<<4096 / RPB, 512>>>((const float4*)x, (float4*)d_out);
}

// round 2
// speedup vs baseline: 1.1133x; 1.1133x over previous
#include <cuda_runtime.h>

typedef unsigned long long u64;

#define NSTEP 256   // C2
#define NTH   256   // threads per block; thread t owns complex elements 4t..4t+3
#define G     4     // f32x2 row-groups (2 batch rows each) -> 8 rows per block

// Per-thread coefficient streams, [step][thread], one extra padded step so the
// prefetch load needs no branch. 6 x (257*256) x 16B = 6.3 MB (fits L2).
#define CSZ ((NSTEP + 1) * NTH)
__device__ float4 gT0[CSZ];  // rotA pair 2t:   (dr, di, or, oi)
__device__ float4 gT1[CSZ];  // rotA pair 2t+1: (dr, di, or, oi)
__device__ float4 gT2[CSZ];  // rotB pair 2t:   (dr, di, or, oi)   local pair (e1,e2)
__device__ float4 gT3[CSZ];  // rotB pair 2t+1: (dr, di, or, oi)   boundary pair (e3, nb_e0)
__device__ float4 gT4[CSZ];  // (ctA[2t], stA[2t], ctA[2t+1], stA[2t+1])
__device__ float4 gT5[CSZ];  // (ctB[2t], stB[2t], ctB[2t-1], stB[2t-1])  [zw pre-shifted]

__device__ __forceinline__ u64 pk2(float x) {
    u64 r; asm("mov.b64 %0, {%1, %1};" : "=l"(r) : "f"(x)); return r;
}
__device__ __forceinline__ u64 pk(float lo, float hi) {
    u64 r; asm("mov.b64 %0, {%1, %2};" : "=l"(r) : "f"(lo), "f"(hi)); return r;
}
__device__ __forceinline__ void upk(u64 v, float& lo, float& hi) {
    asm("mov.b64 {%0, %1}, %2;" : "=f"(lo), "=f"(hi) : "l"(v));
}
__device__ __forceinline__ u64 mul2(u64 a, u64 b) {
    u64 r; asm("mul.rn.f32x2 %0, %1, %2;" : "=l"(r) : "l"(a), "l"(b)); return r;
}
__device__ __forceinline__ u64 fma2(u64 a, u64 b, u64 c) {
    u64 r; asm("fma.rn.f32x2 %0, %1, %2, %3;" : "=l"(r) : "l"(a), "l"(b), "l"(c)); return r;
}

// phi/theta arrays: (H2=512, C2=256) row-major -> [p*256 + c]
__global__ void coeff_kernel(const float* __restrict__ phi0, const float* __restrict__ th0,
                             const float* __restrict__ phi1, const float* __restrict__ th1) {
    int idx = blockIdx.x * blockDim.x + threadIdx.x;
    if (idx >= NSTEP * 512) return;
    int p = idx & 511;     // pair index
    int c = idx >> 9;      // step

    float sp, cp, st, ct;
    sincosf(phi0[p * NSTEP + c], &sp, &cp);
    sincosf(th0[p * NSTEP + c], &st, &ct);
    float4 A = make_float4(cp * ct, sp * ct, -cp * st, -sp * st);
    float ctA = ct, stA = st;

    sincosf(phi1[p * NSTEP + c], &sp, &cp);
    sincosf(th1[p * NSTEP + c], &st, &ct);
    float4 B = make_float4(cp * ct, sp * ct, -cp * st, -sp * st);
    float ctB = ct, stB = st;

    int t = p >> 1;
    int base = c * NTH;
    float* f4 = (float*)gT4;
    float* f5 = (float*)gT5;
    if ((p & 1) == 0) {
        gT0[base + t] = A;
        gT2[base + t] = B;
        f4[(base + t) * 4 + 0] = ctA; f4[(base + t) * 4 + 1] = stA;
        f5[(base + t) * 4 + 0] = ctB; f5[(base + t) * 4 + 1] = stB;
    } else {
        gT1[base + t] = A;
        gT3[base + t] = B;
        f4[(base + t) * 4 + 2] = ctA; f4[(base + t) * 4 + 3] = stA;
        // ct/st of odd pair 2t'+1 is consumed as "previous pair" by thread t'+1 (mod 256)
        int ts = (t + 1) & (NTH - 1);
        f5[(base + ts) * 4 + 2] = ctB; f5[(base + ts) * 4 + 3] = stB;
    }
}

__global__ void __launch_bounds__(NTH, 1)
eunn_kernel(const float4* __restrict__ xin, float4* __restrict__ xout) {
    const int t    = threadIdx.x;
    const int lane = t & 31;
    const int w    = t >> 5;               // 8 warps
    const int row0 = blockIdx.x * (2 * G); // 8 batch rows per block
    const u64 SGN  = 0x8000000080000000ULL;

    u64 e0r[G], e0i[G], e1r[G], e1i[G], e2r[G], e2i[G], e3r[G], e3i[G];
#pragma unroll
    for (int g = 0; g < G; g++) {
        size_t r0 = (size_t)(row0 + 2 * g) * 512;
        size_t r1 = r0 + 512;
        float4 a0 = xin[r0 + 2 * t], a1 = xin[r0 + 2 * t + 1];
        float4 b0 = xin[r1 + 2 * t], b1 = xin[r1 + 2 * t + 1];
        e0r[g] = pk(a0.x, b0.x); e0i[g] = pk(a0.y, b0.y);
        e1r[g] = pk(a0.z, b0.z); e1i[g] = pk(a0.w, b0.w);
        e2r[g] = pk(a1.x, b1.x); e2i[g] = pk(a1.y, b1.y);
        e3r[g] = pk(a1.z, b1.z); e3i[g] = pk(a1.w, b1.w);
    }

    // Double-buffered warp-boundary exchange; one __syncthreads per step.
    __shared__ u64 sE0r[2][G][8], sE0i[2][G][8], sE3r[2][G][8], sE3i[2][G][8];

    float4 c0 = gT0[t], c1 = gT1[t], c2 = gT2[t], c3 = gT3[t], c4 = gT4[t], c5 = gT5[t];

    for (int c = 0; c < NSTEP; c++) {
        // Prefetch next step's coefficients (padded arrays -> no branch)
        const int o = (c + 1) * NTH + t;
        float4 n0 = gT0[o], n1 = gT1[o], n2 = gT2[o], n3 = gT3[o], n4 = gT4[o], n5 = gT5[o];

        // ---- Rotation A: pairs (e0,e1) and (e2,e3), fully local ----
        {
            u64 dr0 = pk2(c0.x), di0 = pk2(c0.y), or0 = pk2(c0.z), oi0 = pk2(c0.w);
            u64 nd0 = di0 ^ SGN, no0 = oi0 ^ SGN, ct0 = pk2(c4.x), st0 = pk2(c4.y);
            u64 dr1 = pk2(c1.x), di1 = pk2(c1.y), or1 = pk2(c1.z), oi1 = pk2(c1.w);
            u64 nd1 = di1 ^ SGN, no1 = oi1 ^ SGN, ct1 = pk2(c4.z), st1 = pk2(c4.w);
#pragma unroll
            for (int g = 0; g < G; g++) {
                u64 ar = mul2(dr0, e0r[g]); ar = fma2(nd0, e0i[g], ar);
                ar = fma2(or0, e1r[g], ar); ar = fma2(no0, e1i[g], ar);
                u64 ai = mul2(dr0, e0i[g]); ai = fma2(di0, e0r[g], ai);
                ai = fma2(or0, e1i[g], ai); ai = fma2(oi0, e1r[g], ai);
                u64 br = mul2(ct0, e1r[g]); br = fma2(st0, e0r[g], br);
                u64 bi = mul2(ct0, e1i[g]); bi = fma2(st0, e0i[g], bi);
                e0r[g] = ar; e0i[g] = ai; e1r[g] = br; e1i[g] = bi;

                u64 cr = mul2(dr1, e2r[g]); cr = fma2(nd1, e2i[g], cr);
                cr = fma2(or1, e3r[g], cr); cr = fma2(no1, e3i[g], cr);
                u64 ci = mul2(dr1, e2i[g]); ci = fma2(di1, e2r[g], ci);
                ci = fma2(or1, e3i[g], ci); ci = fma2(oi1, e3r[g], ci);
                u64 xr = mul2(ct1, e3r[g]); xr = fma2(st1, e2r[g], xr);
                u64 xi = mul2(ct1, e3i[g]); xi = fma2(st1, e2i[g], xi);
                e2r[g] = cr; e2i[g] = ci; e3r[g] = xr; e3i[g] = xi;
            }
        }

        const int buf = c & 1;
        if (lane == 0) {
#pragma unroll
            for (int g = 0; g < G; g++) { sE0r[buf][g][w] = e0r[g]; sE0i[buf][g][w] = e0i[g]; }
        }
        if (lane == 31) {
#pragma unroll
            for (int g = 0; g < G; g++) { sE3r[buf][g][w] = e3r[g]; sE3i[buf][g][w] = e3i[g]; }
        }
        __syncthreads();

        // ---- Rotation B: local pair (e1,e2); boundary pair (e3, e0 of t+1) ----
        {
            u64 dr0 = pk2(c2.x), di0 = pk2(c2.y), or0 = pk2(c2.z), oi0 = pk2(c2.w);
            u64 nd0 = di0 ^ SGN, no0 = oi0 ^ SGN, ct0 = pk2(c5.x), st0 = pk2(c5.y);
            u64 dr1 = pk2(c3.x), di1 = pk2(c3.y), or1 = pk2(c3.z), oi1 = pk2(c3.w);
            u64 nd1 = di1 ^ SGN, no1 = oi1 ^ SGN, ctm = pk2(c5.z), stm = pk2(c5.w);
            const int wn = (w + 1) & 7, wp = (w + 7) & 7;
#pragma unroll
            for (int g = 0; g < G; g++) {
                u64 nbr = __shfl_down_sync(0xffffffffu, e0r[g], 1);
                u64 nbi = __shfl_down_sync(0xffffffffu, e0i[g], 1);
                u64 pvr = __shfl_up_sync(0xffffffffu, e3r[g], 1);
                u64 pvi = __shfl_up_sync(0xffffffffu, e3i[g], 1);
                if (lane == 31) { nbr = sE0r[buf][g][wn]; nbi = sE0i[buf][g][wn]; }
                if (lane == 0)  { pvr = sE3r[buf][g][wp]; pvi = sE3i[buf][g][wp]; }

                // local: e1' = dB0*e1 + oB0*e2 ; e2' = ct0*e2 + st0*e1
                u64 ar = mul2(dr0, e1r[g]); ar = fma2(nd0, e1i[g], ar);
                ar = fma2(or0, e2r[g], ar); ar = fma2(no0, e2i[g], ar);
                u64 ai = mul2(dr0, e1i[g]); ai = fma2(di0, e1r[g], ai);
                ai = fma2(or0, e2i[g], ai); ai = fma2(oi0, e2r[g], ai);
                u64 br = mul2(ct0, e2r[g]); br = fma2(st0, e1r[g], br);
                u64 bi = mul2(ct0, e2i[g]); bi = fma2(st0, e1i[g], bi);

                // boundary: e3' = dB1*e3 + oB1*nb_e0 ; e0' = ctm*e0 + stm*pv_e3
                u64 cr = mul2(dr1, e3r[g]); cr = fma2(nd1, e3i[g], cr);
                cr = fma2(or1, nbr, cr);    cr = fma2(no1, nbi, cr);
                u64 ci = mul2(dr1, e3i[g]); ci = fma2(di1, e3r[g], ci);
                ci = fma2(or1, nbi, ci);    ci = fma2(oi1, nbr, ci);
                u64 zr = mul2(ctm, e0r[g]); zr = fma2(stm, pvr, zr);
                u64 zi = mul2(ctm, e0i[g]); zi = fma2(stm, pvi, zi);

                e1r[g] = ar; e1i[g] = ai; e2r[g] = br; e2i[g] = bi;
                e3r[g] = cr; e3i[g] = ci; e0r[g] = zr; e0i[g] = zi;
            }
        }

        c0 = n0; c1 = n1; c2 = n2; c3 = n3; c4 = n4; c5 = n5;
    }

#pragma unroll
    for (int g = 0; g < G; g++) {
        size_t r0 = (size_t)(row0 + 2 * g) * 512;
        size_t r1 = r0 + 512;
        float a, b;
        float4 o0, o1, p0, p1;
        upk(e0r[g], a, b); o0.x = a; p0.x = b;
        upk(e0i[g], a, b); o0.y = a; p0.y = b;
        upk(e1r[g], a, b); o0.z = a; p0.z = b;
        upk(e1i[g], a, b); o0.w = a; p0.w = b;
        upk(e2r[g], a, b); o1.x = a; p1.x = b;
        upk(e2i[g], a, b); o1.y = a; p1.y = b;
        upk(e3r[g], a, b); o1.z = a; p1.z = b;
        upk(e3i[g], a, b); o1.w = a; p1.w = b;
        xout[r0 + 2 * t]     = o0;
        xout[r0 + 2 * t + 1] = o1;
        xout[r1 + 2 * t]     = p0;
        xout[r1 + 2 * t + 1] = p1;
    }
}

extern "C" void kernel_launch(void* const* d_in, const int* in_sizes, int n_in,
                              void* d_out, int out_size) {
    const float* x    = (const float*)d_in[0];
    const float* phi0 = (const float*)d_in[1];
    const float* th0  = (const float*)d_in[2];
    const float* phi1 = (const float*)d_in[3];
    const float* th1  = (const float*)d_in[4];

    coeff_kernel<<<(NSTEP * 512 + 255) / 256, 256>>>(phi0, th0, phi1, th1);
    eunn_kernel<<<4096 / (2 * G), NTH>>>((const float4*)x, (float4*)d_out);
}

// round 3
// speedup vs baseline: 1.3508x; 1.2134x over previous
#include <cuda_runtime.h>

typedef unsigned long long u64;

#define NSTEP 256   // C2
#define NTH   256   // threads per block; thread t owns complex elements 4t..4t+3
#define G     4     // f32x2 row-groups (2 batch rows each) -> 8 rows per block

// Per-thread coefficient streams, [step][thread]. 6 x (256*256) x 16B = 6.3 MB (fits L2).
#define CSZ (NSTEP * NTH)
__device__ float4 gT0[CSZ];  // rotA pair 2t:   (dr, di, or, oi)
__device__ float4 gT1[CSZ];  // rotA pair 2t+1: (dr, di, or, oi)
__device__ float4 gT2[CSZ];  // rotB pair 2t:   (dr, di, or, oi)   local pair (e1,e2)
__device__ float4 gT3[CSZ];  // rotB pair 2t+1: (dr, di, or, oi)   boundary pair (e3, nb_e0)
__device__ float4 gT4[CSZ];  // (ctA[2t], stA[2t], ctA[2t+1], stA[2t+1])
__device__ float4 gT5[CSZ];  // (ctB[2t], stB[2t], ctB[2t-1], stB[2t-1])  [zw pre-shifted]

__device__ __forceinline__ u64 pk2(float x) {
    u64 r; asm("mov.b64 %0, {%1, %1};" : "=l"(r) : "f"(x)); return r;
}
__device__ __forceinline__ u64 pk(float lo, float hi) {
    u64 r; asm("mov.b64 %0, {%1, %2};" : "=l"(r) : "f"(lo), "f"(hi)); return r;
}
__device__ __forceinline__ void upk(u64 v, float& lo, float& hi) {
    asm("mov.b64 {%0, %1}, %2;" : "=f"(lo), "=f"(hi) : "l"(v));
}
__device__ __forceinline__ u64 mul2(u64 a, u64 b) {
    u64 r; asm("mul.rn.f32x2 %0, %1, %2;" : "=l"(r) : "l"(a), "l"(b)); return r;
}
__device__ __forceinline__ u64 fma2(u64 a, u64 b, u64 c) {
    u64 r; asm("fma.rn.f32x2 %0, %1, %2, %3;" : "=l"(r) : "l"(a), "l"(b), "l"(c)); return r;
}

// phi/theta arrays: (H2=512, C2=256) row-major -> [p*256 + c]
__global__ void coeff_kernel(const float* __restrict__ phi0, const float* __restrict__ th0,
                             const float* __restrict__ phi1, const float* __restrict__ th1) {
    int idx = blockIdx.x * blockDim.x + threadIdx.x;
    if (idx >= NSTEP * 512) return;
    int p = idx & 511;     // pair index
    int c = idx >> 9;      // step

    float sp, cp, st, ct;
    sincosf(phi0[p * NSTEP + c], &sp, &cp);
    sincosf(th0[p * NSTEP + c], &st, &ct);
    float4 A = make_float4(cp * ct, sp * ct, -cp * st, -sp * st);
    float ctA = ct, stA = st;

    sincosf(phi1[p * NSTEP + c], &sp, &cp);
    sincosf(th1[p * NSTEP + c], &st, &ct);
    float4 B = make_float4(cp * ct, sp * ct, -cp * st, -sp * st);
    float ctB = ct, stB = st;

    int t = p >> 1;
    int base = c * NTH;
    float* f4 = (float*)gT4;
    float* f5 = (float*)gT5;
    if ((p & 1) == 0) {
        gT0[base + t] = A;
        gT2[base + t] = B;
        f4[(base + t) * 4 + 0] = ctA; f4[(base + t) * 4 + 1] = stA;
        f5[(base + t) * 4 + 0] = ctB; f5[(base + t) * 4 + 1] = stB;
    } else {
        gT1[base + t] = A;
        gT3[base + t] = B;
        f4[(base + t) * 4 + 2] = ctA; f4[(base + t) * 4 + 3] = stA;
        // ct/st of odd pair 2t'+1 is consumed as "previous pair" by thread t'+1 (mod 256)
        int ts = (t + 1) & (NTH - 1);
        f5[(base + ts) * 4 + 2] = ctB; f5[(base + ts) * 4 + 3] = stB;
    }
}

__global__ void __launch_bounds__(NTH, 2)
eunn_kernel(const float4* __restrict__ xin, float4* __restrict__ xout) {
    const int t    = threadIdx.x;
    const int lane = t & 31;
    const int w    = t >> 5;               // 8 warps
    const int row0 = blockIdx.x * (2 * G); // 8 batch rows per block
    const u64 SGN  = 0x8000000080000000ULL;

    u64 e0r[G], e0i[G], e1r[G], e1i[G], e2r[G], e2i[G], e3r[G], e3i[G];
#pragma unroll
    for (int g = 0; g < G; g++) {
        size_t r0 = (size_t)(row0 + 2 * g) * 512;
        size_t r1 = r0 + 512;
        float4 a0 = xin[r0 + 2 * t], a1 = xin[r0 + 2 * t + 1];
        float4 b0 = xin[r1 + 2 * t], b1 = xin[r1 + 2 * t + 1];
        e0r[g] = pk(a0.x, b0.x); e0i[g] = pk(a0.y, b0.y);
        e1r[g] = pk(a0.z, b0.z); e1i[g] = pk(a0.w, b0.w);
        e2r[g] = pk(a1.x, b1.x); e2i[g] = pk(a1.y, b1.y);
        e3r[g] = pk(a1.z, b1.z); e3i[g] = pk(a1.w, b1.w);
    }

    // Double-buffered warp-boundary exchange; one __syncthreads per step.
    __shared__ u64 sE0r[2][G][8], sE0i[2][G][8], sE3r[2][G][8], sE3i[2][G][8];

    for (int c = 0; c < NSTEP; c++) {
        const int o = c * NTH + t;
        // Issue all 6 coefficient loads up front (MLP=6, one L2 round trip)
        float4 c0 = gT0[o], c1 = gT1[o], c2 = gT2[o], c3 = gT3[o], c4 = gT4[o], c5 = gT5[o];

        // ---- Rotation A, pair class 0: (e0,e1) ----
        {
            u64 dr = pk2(c0.x), di = pk2(c0.y), orr = pk2(c0.z), oi = pk2(c0.w);
            u64 nd = di ^ SGN, no = oi ^ SGN, ct = pk2(c4.x), st = pk2(c4.y);
#pragma unroll
            for (int g = 0; g < G; g++) {
                u64 ar = mul2(dr, e0r[g]); ar = fma2(nd, e0i[g], ar);
                ar = fma2(orr, e1r[g], ar); ar = fma2(no, e1i[g], ar);
                u64 ai = mul2(dr, e0i[g]); ai = fma2(di, e0r[g], ai);
                ai = fma2(orr, e1i[g], ai); ai = fma2(oi, e1r[g], ai);
                u64 br = mul2(ct, e1r[g]); br = fma2(st, e0r[g], br);
                u64 bi = mul2(ct, e1i[g]); bi = fma2(st, e0i[g], bi);
                e0r[g] = ar; e0i[g] = ai; e1r[g] = br; e1i[g] = bi;
            }
        }
        // ---- Rotation A, pair class 1: (e2,e3) ----
        {
            u64 dr = pk2(c1.x), di = pk2(c1.y), orr = pk2(c1.z), oi = pk2(c1.w);
            u64 nd = di ^ SGN, no = oi ^ SGN, ct = pk2(c4.z), st = pk2(c4.w);
#pragma unroll
            for (int g = 0; g < G; g++) {
                u64 cr = mul2(dr, e2r[g]); cr = fma2(nd, e2i[g], cr);
                cr = fma2(orr, e3r[g], cr); cr = fma2(no, e3i[g], cr);
                u64 ci = mul2(dr, e2i[g]); ci = fma2(di, e2r[g], ci);
                ci = fma2(orr, e3i[g], ci); ci = fma2(oi, e3r[g], ci);
                u64 xr = mul2(ct, e3r[g]); xr = fma2(st, e2r[g], xr);
                u64 xi = mul2(ct, e3i[g]); xi = fma2(st, e2i[g], xi);
                e2r[g] = cr; e2i[g] = ci; e3r[g] = xr; e3i[g] = xi;
            }
        }

        // Edge publish (post-rotA values)
        const int buf = c & 1;
        if (lane == 0) {
#pragma unroll
            for (int g = 0; g < G; g++) { sE0r[buf][g][w] = e0r[g]; sE0i[buf][g][w] = e0i[g]; }
        }
        if (lane == 31) {
#pragma unroll
            for (int g = 0; g < G; g++) { sE3r[buf][g][w] = e3r[g]; sE3i[buf][g][w] = e3i[g]; }
        }

        // ---- Rotation B, local pair (e1,e2): no exchange needed, run pre-barrier ----
        {
            u64 dr = pk2(c2.x), di = pk2(c2.y), orr = pk2(c2.z), oi = pk2(c2.w);
            u64 nd = di ^ SGN, no = oi ^ SGN, ct = pk2(c5.x), st = pk2(c5.y);
#pragma unroll
            for (int g = 0; g < G; g++) {
                u64 ar = mul2(dr, e1r[g]); ar = fma2(nd, e1i[g], ar);
                ar = fma2(orr, e2r[g], ar); ar = fma2(no, e2i[g], ar);
                u64 ai = mul2(dr, e1i[g]); ai = fma2(di, e1r[g], ai);
                ai = fma2(orr, e2i[g], ai); ai = fma2(oi, e2r[g], ai);
                u64 br = mul2(ct, e2r[g]); br = fma2(st, e1r[g], br);
                u64 bi = mul2(ct, e2i[g]); bi = fma2(st, e1i[g], bi);
                e1r[g] = ar; e1i[g] = ai; e2r[g] = br; e2i[g] = bi;
            }
        }

        __syncthreads();

        // ---- Rotation B, boundary pair: (e3, next-thread e0) ----
        {
            u64 dr = pk2(c3.x), di = pk2(c3.y), orr = pk2(c3.z), oi = pk2(c3.w);
            u64 nd = di ^ SGN, no = oi ^ SGN, ctm = pk2(c5.z), stm = pk2(c5.w);
            const int wn = (w + 1) & 7, wp = (w + 7) & 7;
#pragma unroll
            for (int g = 0; g < G; g++) {
                u64 nbr = __shfl_down_sync(0xffffffffu, e0r[g], 1);
                u64 nbi = __shfl_down_sync(0xffffffffu, e0i[g], 1);
                u64 pvr = __shfl_up_sync(0xffffffffu, e3r[g], 1);
                u64 pvi = __shfl_up_sync(0xffffffffu, e3i[g], 1);
                if (lane == 31) { nbr = sE0r[buf][g][wn]; nbi = sE0i[buf][g][wn]; }
                if (lane == 0)  { pvr = sE3r[buf][g][wp]; pvi = sE3i[buf][g][wp]; }

                u64 cr = mul2(dr, e3r[g]); cr = fma2(nd, e3i[g], cr);
                cr = fma2(orr, nbr, cr);   cr = fma2(no, nbi, cr);
                u64 ci = mul2(dr, e3i[g]); ci = fma2(di, e3r[g], ci);
                ci = fma2(orr, nbi, ci);   ci = fma2(oi, nbr, ci);
                u64 zr = mul2(ctm, e0r[g]); zr = fma2(stm, pvr, zr);
                u64 zi = mul2(ctm, e0i[g]); zi = fma2(stm, pvi, zi);
                e3r[g] = cr; e3i[g] = ci; e0r[g] = zr; e0i[g] = zi;
            }
        }
    }

#pragma unroll
    for (int g = 0; g < G; g++) {
        size_t r0 = (size_t)(row0 + 2 * g) * 512;
        size_t r1 = r0 + 512;
        float a, b;
        float4 o0, o1, p0, p1;
        upk(e0r[g], a, b); o0.x = a; p0.x = b;
        upk(e0i[g], a, b); o0.y = a; p0.y = b;
        upk(e1r[g], a, b); o0.z = a; p0.z = b;
        upk(e1i[g], a, b); o0.w = a; p0.w = b;
        upk(e2r[g], a, b); o1.x = a; p1.x = b;
        upk(e2i[g], a, b); o1.y = a; p1.y = b;
        upk(e3r[g], a, b); o1.z = a; p1.z = b;
        upk(e3i[g], a, b); o1.w = a; p1.w = b;
        xout[r0 + 2 * t]     = o0;
        xout[r0 + 2 * t + 1] = o1;
        xout[r1 + 2 * t]     = p0;
        xout[r1 + 2 * t + 1] = p1;
    }
}

extern "C" void kernel_launch(void* const* d_in, const int* in_sizes, int n_in,
                              void* d_out, int out_size) {
    const float* x    = (const float*)d_in[0];
    const float* phi0 = (const float*)d_in[1];
    const float* th0  = (const float*)d_in[2];
    const float* phi1 = (const float*)d_in[3];
    const float* th1  = (const float*)d_in[4];

    coeff_kernel<<<(NSTEP * 512 + 255) / 256, 256>>>(phi0, th0, phi1, th1);
    eunn_kernel<<<4096 / (2 * G), NTH>>>((const float4*)x, (float4*)d_out);
}